// round 2
// baseline (speedup 1.0000x reference)
#include <cuda_runtime.h>
#include <cuda_bf16.h>
#include <math.h>

// ---------------------------------------------------------------------------
// Problem constants
// ---------------------------------------------------------------------------
#define S_LEN   2048
#define HID     2048
#define NHEAD   16
#define QLORA   1536
#define KVLORA  512
#define DNOPE   128
#define DROPE   64
#define DV      128
#define DQK     192            // DNOPE + DROPE
#define QDIM    (NHEAD*DQK)    // 3072
#define KVDIM   (NHEAD*(DNOPE+DV)) // 4096
#define CKVDIM  (KVLORA+DROPE) // 576
#define EPSF    1e-6f

// ---------------------------------------------------------------------------
// Static scratch (no allocations allowed)
// ---------------------------------------------------------------------------
__device__ float g_qa  [S_LEN * QLORA];   // hidden @ Wqa (then rmsnormed in place)
__device__ float g_q   [S_LEN * QDIM];    // qa_n @ Wqb  (RoPE applied in place)
__device__ float g_ckv [S_LEN * CKVDIM];  // hidden @ Wkva
__device__ float g_ckvn[S_LEN * KVLORA];  // rmsnorm(ckv[:,:512])
__device__ float g_kv  [S_LEN * KVDIM];   // ckvn @ Wkvb  (k_nope|v interleaved per head)
__device__ float g_kpe [S_LEN * DROPE];   // rope'd shared k_pe
__device__ float g_attn[S_LEN * (NHEAD*DV)]; // attention output, (s, h*128+d)

// ---------------------------------------------------------------------------
// SGEMM: C[M,N] = A[M,K] @ B[K,N], fp32, row-major.
// BM=BN=128, BK=8, 256 threads, 8x8 register tile per thread.
// M % 128 == 0, K % 8 == 0, N % 4 == 0 assumed (true for all calls);
// N edge handled by predication.
// ---------------------------------------------------------------------------
__global__ __launch_bounds__(256) void sgemm_kernel(
    const float* __restrict__ A, const float* __restrict__ B,
    float* __restrict__ C, int M, int N, int K)
{
    constexpr int BM = 128, BN = 128, BK = 8, TM = 8, TN = 8;
    __shared__ float As[BK][BM];
    __shared__ float Bs[BK][BN];

    const int tid = threadIdx.x;
    const int tx  = tid % (BN / TN);   // 0..15
    const int ty  = tid / (BN / TN);   // 0..15
    const int bx  = blockIdx.x;
    const int by  = blockIdx.y;

    // A tile load mapping: one float4 along K per thread
    const int aRow  = tid >> 1;            // 0..127
    const int aCol  = (tid & 1) * 4;       // 0 or 4
    // B tile load mapping: one float4 along N per thread
    const int bRow  = tid >> 5;            // 0..7
    const int bCol  = (tid & 31) * 4;      // 0..124

    const float* Ab = A + (size_t)by * BM * K;
    const int    gcol = bx * BN + bCol;

    float acc[TM][TN];
#pragma unroll
    for (int i = 0; i < TM; i++)
#pragma unroll
        for (int j = 0; j < TN; j++) acc[i][j] = 0.f;

    for (int k0 = 0; k0 < K; k0 += BK) {
        // load A tile (transposed into As)
        float4 a4 = *(const float4*)(Ab + (size_t)aRow * K + k0 + aCol);
        As[aCol + 0][aRow] = a4.x;
        As[aCol + 1][aRow] = a4.y;
        As[aCol + 2][aRow] = a4.z;
        As[aCol + 3][aRow] = a4.w;
        // load B tile (guard N edge; N % 4 == 0 so float4 is all-in or all-out)
        float4 b4 = make_float4(0.f, 0.f, 0.f, 0.f);
        if (gcol < N)
            b4 = *(const float4*)(B + (size_t)(k0 + bRow) * N + gcol);
        *(float4*)&Bs[bRow][bCol] = b4;
        __syncthreads();

#pragma unroll
        for (int kk = 0; kk < BK; kk++) {
            float ar[TM], br[TN];
            *(float4*)&ar[0] = *(const float4*)&As[kk][ty * TM + 0];
            *(float4*)&ar[4] = *(const float4*)&As[kk][ty * TM + 4];
            *(float4*)&br[0] = *(const float4*)&Bs[kk][tx * TN + 0];
            *(float4*)&br[4] = *(const float4*)&Bs[kk][tx * TN + 4];
#pragma unroll
            for (int i = 0; i < TM; i++)
#pragma unroll
                for (int j = 0; j < TN; j++)
                    acc[i][j] += ar[i] * br[j];
        }
        __syncthreads();
    }

#pragma unroll
    for (int i = 0; i < TM; i++) {
        const int row = by * BM + ty * TM + i;
#pragma unroll
        for (int j = 0; j < TN; j += 4) {
            const int col = bx * BN + tx * TN + j;
            if (col < N) {
                float4 v = make_float4(acc[i][j], acc[i][j+1], acc[i][j+2], acc[i][j+3]);
                *(float4*)(C + (size_t)row * N + col) = v;
            }
        }
    }
}

// ---------------------------------------------------------------------------
// RMSNorm over first `ncols` of each row. One block per row.
// ---------------------------------------------------------------------------
__global__ __launch_bounds__(256) void rmsnorm_kernel(
    const float* __restrict__ in, const float* __restrict__ w,
    float* __restrict__ out, int in_stride, int ncols, int out_stride)
{
    const int row = blockIdx.x;
    const float* x = in + (size_t)row * in_stride;
    float ss = 0.f;
    for (int c = threadIdx.x; c < ncols; c += blockDim.x) {
        float v = x[c];
        ss += v * v;
    }
    __shared__ float red[32];
#pragma unroll
    for (int o = 16; o; o >>= 1) ss += __shfl_xor_sync(~0u, ss, o);
    if ((threadIdx.x & 31) == 0) red[threadIdx.x >> 5] = ss;
    __syncthreads();
    if (threadIdx.x < 32) {
        float v = (threadIdx.x < (blockDim.x >> 5)) ? red[threadIdx.x] : 0.f;
#pragma unroll
        for (int o = 16; o; o >>= 1) v += __shfl_xor_sync(~0u, v, o);
        if (threadIdx.x == 0) red[0] = v;
    }
    __syncthreads();
    const float inv = rsqrtf(red[0] / (float)ncols + EPSF);
    float* o = out + (size_t)row * out_stride;
    for (int c = threadIdx.x; c < ncols; c += blockDim.x)
        o[c] = w[c] * x[c] * inv;
}

// ---------------------------------------------------------------------------
// RoPE: grid (S, NHEAD+1), 64 threads.
//  blockIdx.y <  NHEAD : rotate q_pe in place (q[s, h*192 + 128 .. 192))
//  blockIdx.y == NHEAD : rotate k_pe (ckv[s, 512..576)) into g_kpe[s]
// ---------------------------------------------------------------------------
__global__ void rope_kernel(float* __restrict__ q,
                            const float* __restrict__ ckv,
                            float* __restrict__ kpe)
{
    const int s = blockIdx.x;
    const int h = blockIdx.y;
    const int j = threadIdx.x;                 // 0..63
    const float inv_freq = powf(10000.f, -(float)(2 * (j & 31)) / (float)DROPE);
    float sn, cs;
    sincosf((float)s * inv_freq, &sn, &cs);

    if (h < NHEAD) {
        float* p = q + (size_t)s * QDIM + h * DQK + DNOPE;
        const float x  = p[j];
        const float xo = (j < 32) ? p[j + 32] : p[j - 32];
        __syncthreads();                       // all reads before any write
        p[j] = x * cs + ((j < 32) ? -xo : xo) * sn;
    } else {
        const float* p = ckv + (size_t)s * CKVDIM + KVLORA;
        const float x  = p[j];
        const float xo = (j < 32) ? p[j + 32] : p[j - 32];
        kpe[(size_t)s * DROPE + j] = x * cs + ((j < 32) ? -xo : xo) * sn;
    }
}

// ---------------------------------------------------------------------------
// Causal attention, warp-per-query, online softmax, fp32.
// grid (S/4, NHEAD), 128 threads (4 warps). 2 keys per iteration for MLP.
// Q rows: g_q[s, h*192 .. h*192+192)  (nope|rope'd pe, contiguous)
// K row j: nope = g_kv[j, h*256 .. +128), pe = g_kpe[j]
// V row j: g_kv[j, h*256+128 .. +256)
// out: g_attn[s, h*128 + d]
// ---------------------------------------------------------------------------
__global__ __launch_bounds__(128) void attn_kernel(
    const float* __restrict__ q, const float* __restrict__ kv,
    const float* __restrict__ kpe, float* __restrict__ out)
{
    const int warp = threadIdx.x >> 5;
    const int lane = threadIdx.x & 31;
    const int qi   = blockIdx.x * 4 + warp;
    const int h    = blockIdx.y;
    const float scale = rsqrtf((float)DQK);

    const float* qp = q + (size_t)qi * QDIM + h * DQK;
    float qn[6];
#pragma unroll
    for (int i = 0; i < 6; i++) qn[i] = qp[lane + 32 * i] * scale;

    float m = -1e30f, l = 0.f;
    float a0 = 0.f, a1 = 0.f, a2 = 0.f, a3 = 0.f;

    const float* kvh = kv + h * (DNOPE + DV);
    const int nk = qi + 1;
    int j = 0;
    for (; j + 2 <= nk; j += 2) {
        const float* k0 = kvh + (size_t)j * KVDIM;
        const float* k1 = k0 + KVDIM;
        const float* p0 = kpe + (size_t)j * DROPE;
        const float* p1 = p0 + DROPE;

        float s0 = qn[0]*k0[lane]      + qn[1]*k0[lane+32]
                 + qn[2]*k0[lane+64]   + qn[3]*k0[lane+96]
                 + qn[4]*p0[lane]      + qn[5]*p0[lane+32];
        float s1 = qn[0]*k1[lane]      + qn[1]*k1[lane+32]
                 + qn[2]*k1[lane+64]   + qn[3]*k1[lane+96]
                 + qn[4]*p1[lane]      + qn[5]*p1[lane+32];
#pragma unroll
        for (int o = 16; o; o >>= 1) {
            s0 += __shfl_xor_sync(~0u, s0, o);
            s1 += __shfl_xor_sync(~0u, s1, o);
        }
        const float* v0 = k0 + DNOPE;
        const float* v1 = k1 + DNOPE;
        float va0 = v0[lane], va1 = v0[lane+32], va2 = v0[lane+64], va3 = v0[lane+96];
        float vb0 = v1[lane], vb1 = v1[lane+32], vb2 = v1[lane+64], vb3 = v1[lane+96];

        const float mn = fmaxf(m, fmaxf(s0, s1));
        const float c  = __expf(m - mn);
        const float e0 = __expf(s0 - mn);
        const float e1 = __expf(s1 - mn);
        m = mn;
        l = l * c + e0 + e1;
        a0 = a0 * c + e0 * va0 + e1 * vb0;
        a1 = a1 * c + e0 * va1 + e1 * vb1;
        a2 = a2 * c + e0 * va2 + e1 * vb2;
        a3 = a3 * c + e0 * va3 + e1 * vb3;
    }
    if (j < nk) {  // tail key
        const float* k0 = kvh + (size_t)j * KVDIM;
        const float* p0 = kpe + (size_t)j * DROPE;
        float s0 = qn[0]*k0[lane]      + qn[1]*k0[lane+32]
                 + qn[2]*k0[lane+64]   + qn[3]*k0[lane+96]
                 + qn[4]*p0[lane]      + qn[5]*p0[lane+32];
#pragma unroll
        for (int o = 16; o; o >>= 1) s0 += __shfl_xor_sync(~0u, s0, o);
        const float* v0 = k0 + DNOPE;
        const float mn = fmaxf(m, s0);
        const float c  = __expf(m - mn);
        const float e0 = __expf(s0 - mn);
        m = mn;
        l = l * c + e0;
        a0 = a0 * c + e0 * v0[lane];
        a1 = a1 * c + e0 * v0[lane+32];
        a2 = a2 * c + e0 * v0[lane+64];
        a3 = a3 * c + e0 * v0[lane+96];
    }
    const float invl = 1.f / l;
    float* op = out + (size_t)qi * (NHEAD * DV) + h * DV;
    op[lane]      = a0 * invl;
    op[lane + 32] = a1 * invl;
    op[lane + 64] = a2 * invl;
    op[lane + 96] = a3 * invl;
}

// ---------------------------------------------------------------------------
// Launch
// ---------------------------------------------------------------------------
extern "C" void kernel_launch(void* const* d_in, const int* in_sizes, int n_in,
                              void* d_out, int out_size)
{
    const float* hidden = (const float*)d_in[0];  // (1,2048,2048)
    const float* Wqa    = (const float*)d_in[1];  // (2048,1536)
    const float* qln    = (const float*)d_in[2];  // (1536,)
    const float* Wqb    = (const float*)d_in[3];  // (1536,3072)
    const float* Wkva   = (const float*)d_in[4];  // (2048,576)
    const float* kvln   = (const float*)d_in[5];  // (512,)
    const float* Wkvb   = (const float*)d_in[6];  // (512,4096)
    const float* Wo     = (const float*)d_in[7];  // (2048,2048)
    float* out = (float*)d_out;

    float *qa, *qbuf, *ckv, *ckvn, *kvbuf, *kpe, *attn;
    cudaGetSymbolAddress((void**)&qa,    g_qa);
    cudaGetSymbolAddress((void**)&qbuf,  g_q);
    cudaGetSymbolAddress((void**)&ckv,   g_ckv);
    cudaGetSymbolAddress((void**)&ckvn,  g_ckvn);
    cudaGetSymbolAddress((void**)&kvbuf, g_kv);
    cudaGetSymbolAddress((void**)&kpe,   g_kpe);
    cudaGetSymbolAddress((void**)&attn,  g_attn);

    const dim3 blk(256);

    // Q path: hidden @ Wqa -> rmsnorm -> @ Wqb
    sgemm_kernel<<<dim3(QLORA/128, S_LEN/128), blk>>>(hidden, Wqa, qa, S_LEN, QLORA, HID);
    rmsnorm_kernel<<<S_LEN, blk>>>(qa, qln, qa, QLORA, QLORA, QLORA);
    sgemm_kernel<<<dim3(QDIM/128, S_LEN/128), blk>>>(qa, Wqb, qbuf, S_LEN, QDIM, QLORA);

    // KV path: hidden @ Wkva -> rmsnorm(first 512) -> @ Wkvb
    sgemm_kernel<<<dim3((CKVDIM+127)/128, S_LEN/128), blk>>>(hidden, Wkva, ckv, S_LEN, CKVDIM, HID);
    rmsnorm_kernel<<<S_LEN, blk>>>(ckv, kvln, ckvn, CKVDIM, KVLORA, KVLORA);
    sgemm_kernel<<<dim3(KVDIM/128, S_LEN/128), blk>>>(ckvn, Wkvb, kvbuf, S_LEN, KVDIM, KVLORA);

    // RoPE on q_pe (in place) and k_pe (-> g_kpe)
    rope_kernel<<<dim3(S_LEN, NHEAD + 1), 64>>>(qbuf, ckv, kpe);

    // Causal attention
    attn_kernel<<<dim3(S_LEN/4, NHEAD), 128>>>(qbuf, kvbuf, kpe, attn);

    // Output projection
    sgemm_kernel<<<dim3(HID/128, S_LEN/128), blk>>>(attn, Wo, out, S_LEN, HID, HID);
}

// round 3
// speedup vs baseline: 1.3920x; 1.3920x over previous
#include <cuda_runtime.h>
#include <cuda_bf16.h>
#include <math.h>
#include <stdint.h>

// ---------------------------------------------------------------------------
// Problem constants
// ---------------------------------------------------------------------------
#define S_LEN   2048
#define HID     2048
#define NHEAD   16
#define QLORA   1536
#define KVLORA  512
#define DNOPE   128
#define DROPE   64
#define DV      128
#define DQK     192            // DNOPE + DROPE
#define QDIM    (NHEAD*DQK)    // 3072
#define KVDIM   (NHEAD*(DNOPE+DV)) // 4096
#define CKVDIM  (KVLORA+DROPE) // 576
#define EPSF    1e-6f

// ---------------------------------------------------------------------------
// Static scratch (no allocations allowed)
// ---------------------------------------------------------------------------
__device__ float g_qa  [S_LEN * QLORA];
__device__ float g_q   [S_LEN * QDIM];
__device__ float g_ckv [S_LEN * CKVDIM];
__device__ float g_ckvn[S_LEN * KVLORA];
__device__ float g_kv  [S_LEN * KVDIM];
__device__ float g_kpe [S_LEN * DROPE];
__device__ float g_attn[S_LEN * (NHEAD*DV)];

// ---------------------------------------------------------------------------
// Tensor-core GEMM: C[M,N] = A[M,K] @ B[K,N], fp32 in/out.
// bf16 hi/lo split (3-term) on mma.sync.m16n8k16 for ~1e-6 relative accuracy.
// Block tile 128x128xBK16, 8 warps, warp tile 32x64.
// Requires: M%128==0, K%16==0, N%4==0 (N edge predicated).
// ---------------------------------------------------------------------------
#define LDA_S 24    // 16 + 8 pad (bf16 elems) -> 48B rows, conflict-free ldmatrix
#define LDB_S 136   // 128 + 8 pad             -> 272B rows, conflict-free ldmatrix

__device__ __forceinline__ void bf16_split(float x, __nv_bfloat16& h, __nv_bfloat16& l) {
    h = __float2bfloat16_rn(x);
    l = __float2bfloat16_rn(x - __bfloat162float(h));
}

__device__ __forceinline__ void ldsm4(uint32_t* r, const void* p) {
    uint32_t a = (uint32_t)__cvta_generic_to_shared(p);
    asm volatile("ldmatrix.sync.aligned.m8n8.x4.shared.b16 {%0,%1,%2,%3}, [%4];"
                 : "=r"(r[0]), "=r"(r[1]), "=r"(r[2]), "=r"(r[3]) : "r"(a));
}
__device__ __forceinline__ void ldsm4t(uint32_t* r, const void* p) {
    uint32_t a = (uint32_t)__cvta_generic_to_shared(p);
    asm volatile("ldmatrix.sync.aligned.m8n8.x4.trans.shared.b16 {%0,%1,%2,%3}, [%4];"
                 : "=r"(r[0]), "=r"(r[1]), "=r"(r[2]), "=r"(r[3]) : "r"(a));
}
__device__ __forceinline__ void mma16816(float* c, const uint32_t* a, const uint32_t* b) {
    asm volatile("mma.sync.aligned.m16n8k16.row.col.f32.bf16.bf16.f32 "
                 "{%0,%1,%2,%3}, {%4,%5,%6,%7}, {%8,%9}, {%0,%1,%2,%3};"
                 : "+f"(c[0]), "+f"(c[1]), "+f"(c[2]), "+f"(c[3])
                 : "r"(a[0]), "r"(a[1]), "r"(a[2]), "r"(a[3]), "r"(b[0]), "r"(b[1]));
}

__global__ __launch_bounds__(256) void mma_gemm_kernel(
    const float* __restrict__ A, const float* __restrict__ B,
    float* __restrict__ C, int M, int N, int K)
{
    __shared__ __nv_bfloat16 sAh[128][LDA_S];
    __shared__ __nv_bfloat16 sAl[128][LDA_S];
    __shared__ __nv_bfloat16 sBh[16][LDB_S];
    __shared__ __nv_bfloat16 sBl[16][LDB_S];

    const int tid  = threadIdx.x;
    const int lane = tid & 31;
    const int warp = tid >> 5;
    const int wm   = warp >> 1;   // 0..3  (32-row slabs)
    const int wn   = warp & 1;    // 0..1  (64-col slabs)
    const int bx   = blockIdx.x;
    const int by   = blockIdx.y;

    // A global-load map: float4 id i: row=i>>2, col=(i&3)*4 ; thread does i=tid, tid+256
    const int ar = tid >> 2;
    const int ac = (tid & 3) * 4;
    // B global-load map: float4 id i: row=i>>5, col=(i&31)*4 ; thread does i=tid, tid+256
    const int br = tid >> 5;
    const int bc = (tid & 31) * 4;
    const int bgcol = bx * 128 + bc;

    const float* Abase = A + (size_t)(by * 128 + ar) * K + ac;
    const float* Bbase = B + (size_t)br * N + bgcol;

    float acc[2][8][4];
#pragma unroll
    for (int i = 0; i < 2; i++)
#pragma unroll
        for (int j = 0; j < 8; j++)
#pragma unroll
            for (int v = 0; v < 4; v++) acc[i][j][v] = 0.f;

    // ldmatrix addressing (identical index math for A and B tiles)
    const int fr  = lane & 15;           // row within 16
    const int fc8 = (lane >> 4) * 8;     // 0 or 8 column-half

    for (int k0 = 0; k0 < K; k0 += 16) {
        // ---- load + split A tile (128x16) ----
        {
            float4 v = *(const float4*)(Abase + k0);
            __nv_bfloat16 h, l;
            bf16_split(v.x, h, l); sAh[ar][ac+0] = h; sAl[ar][ac+0] = l;
            bf16_split(v.y, h, l); sAh[ar][ac+1] = h; sAl[ar][ac+1] = l;
            bf16_split(v.z, h, l); sAh[ar][ac+2] = h; sAl[ar][ac+2] = l;
            bf16_split(v.w, h, l); sAh[ar][ac+3] = h; sAl[ar][ac+3] = l;
            float4 v2 = *(const float4*)(Abase + (size_t)64 * K + k0);
            bf16_split(v2.x, h, l); sAh[ar+64][ac+0] = h; sAl[ar+64][ac+0] = l;
            bf16_split(v2.y, h, l); sAh[ar+64][ac+1] = h; sAl[ar+64][ac+1] = l;
            bf16_split(v2.z, h, l); sAh[ar+64][ac+2] = h; sAl[ar+64][ac+2] = l;
            bf16_split(v2.w, h, l); sAh[ar+64][ac+3] = h; sAl[ar+64][ac+3] = l;
        }
        // ---- load + split B tile (16x128), N-edge guarded ----
        {
            float4 v = make_float4(0.f, 0.f, 0.f, 0.f);
            float4 v2 = v;
            if (bgcol < N) {
                v  = *(const float4*)(Bbase + (size_t)k0 * N);
                v2 = *(const float4*)(Bbase + (size_t)(k0 + 8) * N);
            }
            __nv_bfloat16 h, l;
            bf16_split(v.x, h, l);  sBh[br][bc+0] = h; sBl[br][bc+0] = l;
            bf16_split(v.y, h, l);  sBh[br][bc+1] = h; sBl[br][bc+1] = l;
            bf16_split(v.z, h, l);  sBh[br][bc+2] = h; sBl[br][bc+2] = l;
            bf16_split(v.w, h, l);  sBh[br][bc+3] = h; sBl[br][bc+3] = l;
            bf16_split(v2.x, h, l); sBh[br+8][bc+0] = h; sBl[br+8][bc+0] = l;
            bf16_split(v2.y, h, l); sBh[br+8][bc+1] = h; sBl[br+8][bc+1] = l;
            bf16_split(v2.z, h, l); sBh[br+8][bc+2] = h; sBl[br+8][bc+2] = l;
            bf16_split(v2.w, h, l); sBh[br+8][bc+3] = h; sBl[br+8][bc+3] = l;
        }
        __syncthreads();

        // ---- A fragments for this warp's two m16 tiles ----
        uint32_t ah[2][4], al[2][4];
        const int am = wm * 32 + fr;
        ldsm4(ah[0], &sAh[am][fc8]);
        ldsm4(ah[1], &sAh[am + 16][fc8]);
        ldsm4(al[0], &sAl[am][fc8]);
        ldsm4(al[1], &sAl[am + 16][fc8]);

        // ---- sweep the warp's 64 columns as 4 n16 chunks ----
#pragma unroll
        for (int nt = 0; nt < 4; nt++) {
            const int bn = wn * 64 + nt * 16 + fc8;
            uint32_t bh[4], bl[4];
            ldsm4t(bh, &sBh[fr][bn]);
            ldsm4t(bl, &sBl[fr][bn]);
#pragma unroll
            for (int mt = 0; mt < 2; mt++) {
                mma16816(acc[mt][2*nt],     ah[mt], bh);
                mma16816(acc[mt][2*nt],     ah[mt], bl);
                mma16816(acc[mt][2*nt],     al[mt], bh);
                mma16816(acc[mt][2*nt+1],   ah[mt], bh + 2);
                mma16816(acc[mt][2*nt+1],   ah[mt], bl + 2);
                mma16816(acc[mt][2*nt+1],   al[mt], bh + 2);
            }
        }
        __syncthreads();
    }

    // ---- epilogue ----
#pragma unroll
    for (int mt = 0; mt < 2; mt++) {
        const int row = by * 128 + wm * 32 + mt * 16 + (lane >> 2);
#pragma unroll
        for (int nt8 = 0; nt8 < 8; nt8++) {
            const int col = bx * 128 + wn * 64 + nt8 * 8 + (lane & 3) * 2;
            if (col < N) {
                *(float2*)(C + (size_t)row * N + col) =
                    make_float2(acc[mt][nt8][0], acc[mt][nt8][1]);
                *(float2*)(C + (size_t)(row + 8) * N + col) =
                    make_float2(acc[mt][nt8][2], acc[mt][nt8][3]);
            }
        }
    }
}

// ---------------------------------------------------------------------------
// RMSNorm over first `ncols` of each row. One block per row.
// ---------------------------------------------------------------------------
__global__ __launch_bounds__(256) void rmsnorm_kernel(
    const float* __restrict__ in, const float* __restrict__ w,
    float* __restrict__ out, int in_stride, int ncols, int out_stride)
{
    const int row = blockIdx.x;
    const float* x = in + (size_t)row * in_stride;
    float ss = 0.f;
    for (int c = threadIdx.x; c < ncols; c += blockDim.x) {
        float v = x[c];
        ss += v * v;
    }
    __shared__ float red[32];
#pragma unroll
    for (int o = 16; o; o >>= 1) ss += __shfl_xor_sync(~0u, ss, o);
    if ((threadIdx.x & 31) == 0) red[threadIdx.x >> 5] = ss;
    __syncthreads();
    if (threadIdx.x < 32) {
        float v = (threadIdx.x < (blockDim.x >> 5)) ? red[threadIdx.x] : 0.f;
#pragma unroll
        for (int o = 16; o; o >>= 1) v += __shfl_xor_sync(~0u, v, o);
        if (threadIdx.x == 0) red[0] = v;
    }
    __syncthreads();
    const float inv = rsqrtf(red[0] / (float)ncols + EPSF);
    float* o = out + (size_t)row * out_stride;
    for (int c = threadIdx.x; c < ncols; c += blockDim.x)
        o[c] = w[c] * x[c] * inv;
}

// ---------------------------------------------------------------------------
// RoPE: grid (S, NHEAD+1), 64 threads.
// ---------------------------------------------------------------------------
__global__ void rope_kernel(float* __restrict__ q,
                            const float* __restrict__ ckv,
                            float* __restrict__ kpe)
{
    const int s = blockIdx.x;
    const int h = blockIdx.y;
    const int j = threadIdx.x;                 // 0..63
    const float inv_freq = powf(10000.f, -(float)(2 * (j & 31)) / (float)DROPE);
    float sn, cs;
    sincosf((float)s * inv_freq, &sn, &cs);

    if (h < NHEAD) {
        float* p = q + (size_t)s * QDIM + h * DQK + DNOPE;
        const float x  = p[j];
        const float xo = (j < 32) ? p[j + 32] : p[j - 32];
        __syncthreads();
        p[j] = x * cs + ((j < 32) ? -xo : xo) * sn;
    } else {
        const float* p = ckv + (size_t)s * CKVDIM + KVLORA;
        const float x  = p[j];
        const float xo = (j < 32) ? p[j + 32] : p[j - 32];
        kpe[(size_t)s * DROPE + j] = x * cs + ((j < 32) ? -xo : xo) * sn;
    }
}

// ---------------------------------------------------------------------------
// Causal attention, warp-per-query, online softmax, fp32.
// ---------------------------------------------------------------------------
__global__ __launch_bounds__(128) void attn_kernel(
    const float* __restrict__ q, const float* __restrict__ kv,
    const float* __restrict__ kpe, float* __restrict__ out)
{
    const int warp = threadIdx.x >> 5;
    const int lane = threadIdx.x & 31;
    const int qi   = blockIdx.x * 4 + warp;
    const int h    = blockIdx.y;
    const float scale = rsqrtf((float)DQK);

    const float* qp = q + (size_t)qi * QDIM + h * DQK;
    float qn[6];
#pragma unroll
    for (int i = 0; i < 6; i++) qn[i] = qp[lane + 32 * i] * scale;

    float m = -1e30f, l = 0.f;
    float a0 = 0.f, a1 = 0.f, a2 = 0.f, a3 = 0.f;

    const float* kvh = kv + h * (DNOPE + DV);
    const int nk = qi + 1;
    int j = 0;
    for (; j + 2 <= nk; j += 2) {
        const float* k0 = kvh + (size_t)j * KVDIM;
        const float* k1 = k0 + KVDIM;
        const float* p0 = kpe + (size_t)j * DROPE;
        const float* p1 = p0 + DROPE;

        float s0 = qn[0]*k0[lane]      + qn[1]*k0[lane+32]
                 + qn[2]*k0[lane+64]   + qn[3]*k0[lane+96]
                 + qn[4]*p0[lane]      + qn[5]*p0[lane+32];
        float s1 = qn[0]*k1[lane]      + qn[1]*k1[lane+32]
                 + qn[2]*k1[lane+64]   + qn[3]*k1[lane+96]
                 + qn[4]*p1[lane]      + qn[5]*p1[lane+32];
#pragma unroll
        for (int o = 16; o; o >>= 1) {
            s0 += __shfl_xor_sync(~0u, s0, o);
            s1 += __shfl_xor_sync(~0u, s1, o);
        }
        const float* v0 = k0 + DNOPE;
        const float* v1 = k1 + DNOPE;
        float va0 = v0[lane], va1 = v0[lane+32], va2 = v0[lane+64], va3 = v0[lane+96];
        float vb0 = v1[lane], vb1 = v1[lane+32], vb2 = v1[lane+64], vb3 = v1[lane+96];

        const float mn = fmaxf(m, fmaxf(s0, s1));
        const float c  = __expf(m - mn);
        const float e0 = __expf(s0 - mn);
        const float e1 = __expf(s1 - mn);
        m = mn;
        l = l * c + e0 + e1;
        a0 = a0 * c + e0 * va0 + e1 * vb0;
        a1 = a1 * c + e0 * va1 + e1 * vb1;
        a2 = a2 * c + e0 * va2 + e1 * vb2;
        a3 = a3 * c + e0 * va3 + e1 * vb3;
    }
    if (j < nk) {
        const float* k0 = kvh + (size_t)j * KVDIM;
        const float* p0 = kpe + (size_t)j * DROPE;
        float s0 = qn[0]*k0[lane]      + qn[1]*k0[lane+32]
                 + qn[2]*k0[lane+64]   + qn[3]*k0[lane+96]
                 + qn[4]*p0[lane]      + qn[5]*p0[lane+32];
#pragma unroll
        for (int o = 16; o; o >>= 1) s0 += __shfl_xor_sync(~0u, s0, o);
        const float* v0 = k0 + DNOPE;
        const float mn = fmaxf(m, s0);
        const float c  = __expf(m - mn);
        const float e0 = __expf(s0 - mn);
        m = mn;
        l = l * c + e0;
        a0 = a0 * c + e0 * v0[lane];
        a1 = a1 * c + e0 * v0[lane+32];
        a2 = a2 * c + e0 * v0[lane+64];
        a3 = a3 * c + e0 * v0[lane+96];
    }
    const float invl = 1.f / l;
    float* op = out + (size_t)qi * (NHEAD * DV) + h * DV;
    op[lane]      = a0 * invl;
    op[lane + 32] = a1 * invl;
    op[lane + 64] = a2 * invl;
    op[lane + 96] = a3 * invl;
}

// ---------------------------------------------------------------------------
// Launch
// ---------------------------------------------------------------------------
extern "C" void kernel_launch(void* const* d_in, const int* in_sizes, int n_in,
                              void* d_out, int out_size)
{
    const float* hidden = (const float*)d_in[0];
    const float* Wqa    = (const float*)d_in[1];
    const float* qln    = (const float*)d_in[2];
    const float* Wqb    = (const float*)d_in[3];
    const float* Wkva   = (const float*)d_in[4];
    const float* kvln   = (const float*)d_in[5];
    const float* Wkvb   = (const float*)d_in[6];
    const float* Wo     = (const float*)d_in[7];
    float* out = (float*)d_out;

    float *qa, *qbuf, *ckv, *ckvn, *kvbuf, *kpe, *attn;
    cudaGetSymbolAddress((void**)&qa,    g_qa);
    cudaGetSymbolAddress((void**)&qbuf,  g_q);
    cudaGetSymbolAddress((void**)&ckv,   g_ckv);
    cudaGetSymbolAddress((void**)&ckvn,  g_ckvn);
    cudaGetSymbolAddress((void**)&kvbuf, g_kv);
    cudaGetSymbolAddress((void**)&kpe,   g_kpe);
    cudaGetSymbolAddress((void**)&attn,  g_attn);

    const dim3 blk(256);

    // Q path
    mma_gemm_kernel<<<dim3(QLORA/128, S_LEN/128), blk>>>(hidden, Wqa, qa, S_LEN, QLORA, HID);
    rmsnorm_kernel<<<S_LEN, blk>>>(qa, qln, qa, QLORA, QLORA, QLORA);
    mma_gemm_kernel<<<dim3(QDIM/128, S_LEN/128), blk>>>(qa, Wqb, qbuf, S_LEN, QDIM, QLORA);

    // KV path
    mma_gemm_kernel<<<dim3((CKVDIM+127)/128, S_LEN/128), blk>>>(hidden, Wkva, ckv, S_LEN, CKVDIM, HID);
    rmsnorm_kernel<<<S_LEN, blk>>>(ckv, kvln, ckvn, CKVDIM, KVLORA, KVLORA);
    mma_gemm_kernel<<<dim3(KVDIM/128, S_LEN/128), blk>>>(ckvn, Wkvb, kvbuf, S_LEN, KVDIM, KVLORA);

    // RoPE
    rope_kernel<<<dim3(S_LEN, NHEAD + 1), 64>>>(qbuf, ckv, kpe);

    // Attention
    attn_kernel<<<dim3(S_LEN/4, NHEAD), 128>>>(qbuf, kvbuf, kpe, attn);

    // Output projection
    mma_gemm_kernel<<<dim3(HID/128, S_LEN/128), blk>>>(attn, Wo, out, S_LEN, HID, HID);
}